// round 4
// baseline (speedup 1.0000x reference)
#include <cuda_runtime.h>
#include <cuda_bf16.h>
#include <cstdint>

// Problem constants (match reference_code)
#define NN 50000
#define EE 800000
#define FIN 256
#define FOUT 64

// Scratch (no cudaMalloc allowed) — static __device__ globals.
__device__ int   g_cnt[NN];          // in-degree (w/o self loop)
__device__ int   g_fill[NN];         // bucket fill cursor
__device__ int   g_off[NN + 1];      // CSR offsets
__device__ int   g_nbr[EE];          // CSR: src node per incoming edge
__device__ float g_deg[NN];          // dinv = rsqrt(deg)
__device__ float g_h[NN * FOUT];     // h = x @ W

// ---------------------------------------------------------------------------
// K1: zero counters
__global__ void k_zero() {
    int i = blockIdx.x * blockDim.x + threadIdx.x;
    if (i < NN) { g_cnt[i] = 0; g_fill[i] = 0; }
}

// K2: in-degree count over edge dst
__global__ void k_count(const int* __restrict__ dst) {
    int e = blockIdx.x * blockDim.x + threadIdx.x;
    if (e < EE) atomicAdd(&g_cnt[dst[e]], 1);
}

// K3: single-block exclusive scan of g_cnt -> g_off, plus dinv = rsqrt(cnt+1)
__global__ __launch_bounds__(1024) void k_scan() {
    __shared__ int sums[1024];
    const int t = threadIdx.x;
    const int CH = (NN + 1023) / 1024;   // 49
    const int base = t * CH;

    int s = 0;
#pragma unroll 7
    for (int i = 0; i < CH; ++i) {
        int idx = base + i;
        if (idx < NN) s += g_cnt[idx];
    }
    sums[t] = s;
    __syncthreads();

    // Hillis-Steele inclusive scan over 1024 partials
    for (int off = 1; off < 1024; off <<= 1) {
        int v = (t >= off) ? sums[t - off] : 0;
        __syncthreads();
        sums[t] += v;
        __syncthreads();
    }

    int run = (t == 0) ? 0 : sums[t - 1];
#pragma unroll 7
    for (int i = 0; i < CH; ++i) {
        int idx = base + i;
        if (idx < NN) {
            int c = g_cnt[idx];
            g_off[idx] = run;
            run += c;
            g_deg[idx] = rsqrtf((float)(c + 1));
        }
    }
    if (t == 1023) g_off[NN] = run;    // == EE
}

// K4: bucket fill — CSR neighbor lists (src ids)
__global__ void k_fill(const int* __restrict__ src, const int* __restrict__ dst) {
    int e = blockIdx.x * blockDim.x + threadIdx.x;
    if (e >= EE) return;
    int s = src[e];
    int d = dst[e];
    int pos = g_off[d] + atomicAdd(&g_fill[d], 1);
    g_nbr[pos] = s;
}

// ---------------------------------------------------------------------------
// K5: mma.sync bf16 GEMM  h = x @ W  with split-bf16:
//   x = x_hi + x_lo, W = W_hi + W_lo; h ≈ x_hi*W_hi + x_hi*W_lo + x_lo*W_hi
// CTA: 128 rows, 512 threads (16 warps: 8 m-stripes x 2 n-halves).

#define PAD_K 264   // 256 + 8 pad: conflict-free b-frag LDS
#define B_HI_OFF 0
#define B_LO_OFF (64 * PAD_K)               // in ushort units
#define GEMM_SMEM (2 * 64 * PAD_K * 2)      // bytes = 67584

__device__ __forceinline__ void mma_bf16(float* c, const uint32_t* a, uint32_t b0, uint32_t b1) {
    asm volatile(
        "mma.sync.aligned.m16n8k16.row.col.f32.bf16.bf16.f32 "
        "{%0,%1,%2,%3}, {%4,%5,%6,%7}, {%8,%9}, {%0,%1,%2,%3};"
        : "+f"(c[0]), "+f"(c[1]), "+f"(c[2]), "+f"(c[3])
        : "r"(a[0]), "r"(a[1]), "r"(a[2]), "r"(a[3]), "r"(b0), "r"(b1));
}

__global__ __launch_bounds__(512, 2) void k_gemm_mma(
    const float* __restrict__ x, const float* __restrict__ W)
{
    extern __shared__ __align__(16) ushort Bs[];   // [2][64][PAD_K] bf16 bits

    const int t    = threadIdx.x;
    const int wid  = t >> 5;
    const int lane = t & 31;
    const int g    = lane >> 2;     // group id (0..7)
    const int tig  = lane & 3;      // thread in group

    // ---- stage W -> smem bf16 hi/lo, [n][k] layout ----
#pragma unroll 8
    for (int it = 0; it < 32; ++it) {
        int idx = t + it * 512;
        int k = idx >> 6;           // 0..255
        int n = idx & 63;           // 0..63
        float w = W[k * FOUT + n];
        __nv_bfloat16 hb = __float2bfloat16(w);
        float hf = __bfloat162float(hb);
        __nv_bfloat16 lb = __float2bfloat16(w - hf);
        Bs[B_HI_OFF + n * PAD_K + k] = __bfloat16_as_ushort(hb);
        Bs[B_LO_OFF + n * PAD_K + k] = __bfloat16_as_ushort(lb);
    }
    __syncthreads();

    // ---- warp tiling ----
    const int stripe = wid & 7;         // m-stripe (16 rows)
    const int nhalf  = wid >> 3;        // 0/1 -> n 0..31 / 32..63
    const int row0   = blockIdx.x * 128 + stripe * 16;

    const int row1 = row0 + g;
    const int row2 = row1 + 8;
    const bool v1 = (row1 < NN);
    const bool v2 = (row2 < NN);
    const float* xr1 = x + (size_t)row1 * FIN;
    const float* xr2 = x + (size_t)row2 * FIN;

    float acc[4][4];
#pragma unroll
    for (int i = 0; i < 4; ++i)
#pragma unroll
        for (int j = 0; j < 4; ++j) acc[i][j] = 0.0f;

    // ---- K loop: 16 steps of k16 ----
#pragma unroll 4
    for (int s = 0; s < 16; ++s) {
        const int kb = s * 16 + tig * 2;

        float2 p0 = v1 ? *reinterpret_cast<const float2*>(xr1 + kb)
                       : make_float2(0.f, 0.f);
        float2 p1 = v2 ? *reinterpret_cast<const float2*>(xr2 + kb)
                       : make_float2(0.f, 0.f);
        float2 p2 = v1 ? *reinterpret_cast<const float2*>(xr1 + kb + 8)
                       : make_float2(0.f, 0.f);
        float2 p3 = v2 ? *reinterpret_cast<const float2*>(xr2 + kb + 8)
                       : make_float2(0.f, 0.f);

        uint32_t a_hi[4], a_lo[4];
        {
            __nv_bfloat16 h;
            float hf, l;
            h = __float2bfloat16(p0.x); hf = __bfloat162float(h); l = p0.x - hf;
            __nv_bfloat16 h2 = __float2bfloat16(p0.y); float hf2 = __bfloat162float(h2);
            a_hi[0] = (uint32_t)__bfloat16_as_ushort(h) | ((uint32_t)__bfloat16_as_ushort(h2) << 16);
            a_lo[0] = (uint32_t)__bfloat16_as_ushort(__float2bfloat16(l)) |
                      ((uint32_t)__bfloat16_as_ushort(__float2bfloat16(p0.y - hf2)) << 16);
            h = __float2bfloat16(p1.x); hf = __bfloat162float(h); l = p1.x - hf;
            h2 = __float2bfloat16(p1.y); hf2 = __bfloat162float(h2);
            a_hi[1] = (uint32_t)__bfloat16_as_ushort(h) | ((uint32_t)__bfloat16_as_ushort(h2) << 16);
            a_lo[1] = (uint32_t)__bfloat16_as_ushort(__float2bfloat16(l)) |
                      ((uint32_t)__bfloat16_as_ushort(__float2bfloat16(p1.y - hf2)) << 16);
            h = __float2bfloat16(p2.x); hf = __bfloat162float(h); l = p2.x - hf;
            h2 = __float2bfloat16(p2.y); hf2 = __bfloat162float(h2);
            a_hi[2] = (uint32_t)__bfloat16_as_ushort(h) | ((uint32_t)__bfloat16_as_ushort(h2) << 16);
            a_lo[2] = (uint32_t)__bfloat16_as_ushort(__float2bfloat16(l)) |
                      ((uint32_t)__bfloat16_as_ushort(__float2bfloat16(p2.y - hf2)) << 16);
            h = __float2bfloat16(p3.x); hf = __bfloat162float(h); l = p3.x - hf;
            h2 = __float2bfloat16(p3.y); hf2 = __bfloat162float(h2);
            a_hi[3] = (uint32_t)__bfloat16_as_ushort(h) | ((uint32_t)__bfloat16_as_ushort(h2) << 16);
            a_lo[3] = (uint32_t)__bfloat16_as_ushort(__float2bfloat16(l)) |
                      ((uint32_t)__bfloat16_as_ushort(__float2bfloat16(p3.y - hf2)) << 16);
        }

#pragma unroll
        for (int nt = 0; nt < 4; ++nt) {
            int n = nhalf * 32 + nt * 8 + g;
            const ushort* bh = &Bs[B_HI_OFF + n * PAD_K + kb];
            const ushort* bl = &Bs[B_LO_OFF + n * PAD_K + kb];
            uint32_t bh0 = *reinterpret_cast<const uint32_t*>(bh);
            uint32_t bh1 = *reinterpret_cast<const uint32_t*>(bh + 8);
            uint32_t bl0 = *reinterpret_cast<const uint32_t*>(bl);
            uint32_t bl1 = *reinterpret_cast<const uint32_t*>(bl + 8);
            mma_bf16(acc[nt], a_hi, bh0, bh1);
            mma_bf16(acc[nt], a_hi, bl0, bl1);
            mma_bf16(acc[nt], a_lo, bh0, bh1);
        }
    }

    // ---- epilogue: write h only (self-loop handled in gather) ----
#pragma unroll
    for (int nt = 0; nt < 4; ++nt) {
        int c0 = nhalf * 32 + nt * 8 + tig * 2;
        if (v1)
            *reinterpret_cast<float2*>(&g_h[(size_t)row1 * FOUT + c0]) =
                make_float2(acc[nt][0], acc[nt][1]);
        if (v2)
            *reinterpret_cast<float2*>(&g_h[(size_t)row2 * FOUT + c0]) =
                make_float2(acc[nt][2], acc[nt][3]);
    }
}

// ---------------------------------------------------------------------------
// K6: warp-per-node CSR gather + self loop + bias + relu
__global__ __launch_bounds__(256) void k_gather(
    const float* __restrict__ bias, float* __restrict__ out)
{
    int node = blockIdx.x * 8 + (threadIdx.x >> 5);
    if (node >= NN) return;
    const int lane = threadIdx.x & 31;

    const float dinv = g_deg[node];
    const int beg = g_off[node];
    const int end = g_off[node + 1];

    // self-loop term: h[node] * dinv^2
    float2 a = *reinterpret_cast<const float2*>(&g_h[(size_t)node * FOUT + lane * 2]);
    const float sl = dinv * dinv;
    a.x *= sl; a.y *= sl;

    int j = beg;
    for (; j + 2 <= end; j += 2) {
        int s0 = g_nbr[j];
        int s1 = g_nbr[j + 1];
        float n0 = dinv * g_deg[s0];
        float n1 = dinv * g_deg[s1];
        float2 v0 = *reinterpret_cast<const float2*>(&g_h[(size_t)s0 * FOUT + lane * 2]);
        float2 v1 = *reinterpret_cast<const float2*>(&g_h[(size_t)s1 * FOUT + lane * 2]);
        a.x = fmaf(v0.x, n0, a.x);
        a.y = fmaf(v0.y, n0, a.y);
        a.x = fmaf(v1.x, n1, a.x);
        a.y = fmaf(v1.y, n1, a.y);
    }
    if (j < end) {
        int s0 = g_nbr[j];
        float n0 = dinv * g_deg[s0];
        float2 v0 = *reinterpret_cast<const float2*>(&g_h[(size_t)s0 * FOUT + lane * 2]);
        a.x = fmaf(v0.x, n0, a.x);
        a.y = fmaf(v0.y, n0, a.y);
    }

    float2 bb = *reinterpret_cast<const float2*>(bias + lane * 2);
    a.x = fmaxf(a.x + bb.x, 0.f);
    a.y = fmaxf(a.y + bb.y, 0.f);
    *reinterpret_cast<float2*>(&out[(size_t)node * FOUT + lane * 2]) = a;
}

// ---------------------------------------------------------------------------
extern "C" void kernel_launch(void* const* d_in, const int* in_sizes, int n_in,
                              void* d_out, int out_size)
{
    const float* x   = (const float*)d_in[0];   // [N, 256]
    const int*   adj = (const int*)d_in[1];     // [2, E]
    const float* W   = (const float*)d_in[2];   // [256, 64]
    const float* b   = (const float*)d_in[3];   // [64]
    float*       out = (float*)d_out;           // [N, 64]

    const int* src = adj;
    const int* dst = adj + EE;

    static bool attr_set = false;
    if (!attr_set) {
        cudaFuncSetAttribute(k_gemm_mma,
                             cudaFuncAttributeMaxDynamicSharedMemorySize, GEMM_SMEM);
        attr_set = true;
    }

    // CSR build
    k_zero<<<(NN + 255) / 256, 256>>>();
    k_count<<<(EE + 255) / 256, 256>>>(dst);
    k_scan<<<1, 1024>>>();
    k_fill<<<(EE + 255) / 256, 256>>>(src, dst);

    // GEMM (mma.sync bf16 split)
    k_gemm_mma<<<(NN + 127) / 128, 512, GEMM_SMEM>>>(x, W);

    // fused gather + self loop + bias + relu
    k_gather<<<(NN + 7) / 8, 256>>>(b, out);
}

// round 5
// speedup vs baseline: 1.8230x; 1.8230x over previous
#include <cuda_runtime.h>
#include <cuda_bf16.h>
#include <cstdint>

// Problem constants (match reference_code)
#define NN 50000
#define EE 800000
#define FIN 256
#define FOUT 64

#define NBLK 49   // ceil(NN / 1024)

// Scratch (no cudaMalloc allowed) — static __device__ globals.
__device__ int   g_cnt[NN];          // in-degree (w/o self loop)
__device__ int   g_fill[NN];         // bucket fill cursor (pre-init to offsets)
__device__ int   g_off[NN + 1];      // CSR offsets
__device__ int   g_bsum[64];         // per-block sums for scan
__device__ int   g_bpre[64];         // per-block exclusive prefixes
__device__ int   g_nbr[EE];          // CSR: src node per incoming edge
__device__ float g_deg[NN];          // dinv = rsqrt(deg)
__device__ float g_h[NN * FOUT];     // h = x @ W

// ---------------------------------------------------------------------------
// K1: zero counters
__global__ void k_zero() {
    int i = blockIdx.x * blockDim.x + threadIdx.x;
    if (i < NN) g_cnt[i] = 0;
}

// K2: in-degree count over edge dst (4 edges/thread, int4 loads)
__global__ void k_count(const int* __restrict__ dst) {
    int e0 = (blockIdx.x * blockDim.x + threadIdx.x) * 4;
    if (e0 >= EE) return;
    int4 d4 = *reinterpret_cast<const int4*>(dst + e0);
    atomicAdd(&g_cnt[d4.x], 1);
    atomicAdd(&g_cnt[d4.y], 1);
    atomicAdd(&g_cnt[d4.z], 1);
    atomicAdd(&g_cnt[d4.w], 1);
}

// K3a: per-block (1024 elems) sums, coalesced
__global__ __launch_bounds__(1024) void k_scan_a() {
    __shared__ int ws[32];
    const int t = threadIdx.x;
    int idx = blockIdx.x * 1024 + t;
    int v = (idx < NN) ? g_cnt[idx] : 0;
    // warp reduce
    for (int o = 16; o > 0; o >>= 1) v += __shfl_down_sync(0xffffffffu, v, o);
    if ((t & 31) == 0) ws[t >> 5] = v;
    __syncthreads();
    if (t < 32) {
        int s = ws[t];
        for (int o = 16; o > 0; o >>= 1) s += __shfl_down_sync(0xffffffffu, s, o);
        if (t == 0) g_bsum[blockIdx.x] = s;
    }
}

// K3b: scan 49 block sums (tiny, 64 threads)
__global__ void k_scan_b() {
    __shared__ int sm[64];
    const int t = threadIdx.x;
    int v = (t < NBLK) ? g_bsum[t] : 0;
    sm[t] = v;
    __syncthreads();
    for (int o = 1; o < 64; o <<= 1) {
        int u = (t >= o) ? sm[t - o] : 0;
        __syncthreads();
        sm[t] += u;
        __syncthreads();
    }
    if (t < NBLK) g_bpre[t] = sm[t] - v;   // exclusive
    if (t == 0) g_off[NN] = EE;
}

// K3c: per-block exclusive scan -> g_off, g_fill (cursor), g_deg
__global__ __launch_bounds__(1024) void k_scan_c() {
    __shared__ int ws[32];
    const int t = threadIdx.x;
    const int lane = t & 31;
    const int wid = t >> 5;
    int idx = blockIdx.x * 1024 + t;
    int c = (idx < NN) ? g_cnt[idx] : 0;

    int incl = c;
    for (int o = 1; o < 32; o <<= 1) {
        int u = __shfl_up_sync(0xffffffffu, incl, o);
        if (lane >= o) incl += u;
    }
    if (lane == 31) ws[wid] = incl;
    __syncthreads();
    if (wid == 0) {
        int wv = (lane < 32) ? ws[lane] : 0;
        for (int o = 1; o < 32; o <<= 1) {
            int u = __shfl_up_sync(0xffffffffu, wv, o);
            if (lane >= o) wv += u;
        }
        ws[lane] = wv;   // inclusive warp sums
    }
    __syncthreads();
    int excl = incl - c + (wid ? ws[wid - 1] : 0);

    if (idx < NN) {
        int off = g_bpre[blockIdx.x] + excl;
        g_off[idx]  = off;
        g_fill[idx] = off;
        g_deg[idx]  = rsqrtf((float)(c + 1));
    }
}

// K4: bucket fill — cursor already holds offsets; 4 edges/thread
__global__ void k_fill(const int* __restrict__ src, const int* __restrict__ dst) {
    int e0 = (blockIdx.x * blockDim.x + threadIdx.x) * 4;
    if (e0 >= EE) return;
    int4 s4 = *reinterpret_cast<const int4*>(src + e0);
    int4 d4 = *reinterpret_cast<const int4*>(dst + e0);
    int p0 = atomicAdd(&g_fill[d4.x], 1);
    int p1 = atomicAdd(&g_fill[d4.y], 1);
    int p2 = atomicAdd(&g_fill[d4.z], 1);
    int p3 = atomicAdd(&g_fill[d4.w], 1);
    g_nbr[p0] = s4.x;
    g_nbr[p1] = s4.y;
    g_nbr[p2] = s4.z;
    g_nbr[p3] = s4.w;
}

// ---------------------------------------------------------------------------
// K5: mma.sync bf16 GEMM  h = x @ W  with split-bf16 (unchanged from R3)
#define PAD_K 264
#define B_HI_OFF 0
#define B_LO_OFF (64 * PAD_K)
#define GEMM_SMEM (2 * 64 * PAD_K * 2)

__device__ __forceinline__ void mma_bf16(float* c, const uint32_t* a, uint32_t b0, uint32_t b1) {
    asm volatile(
        "mma.sync.aligned.m16n8k16.row.col.f32.bf16.bf16.f32 "
        "{%0,%1,%2,%3}, {%4,%5,%6,%7}, {%8,%9}, {%0,%1,%2,%3};"
        : "+f"(c[0]), "+f"(c[1]), "+f"(c[2]), "+f"(c[3])
        : "r"(a[0]), "r"(a[1]), "r"(a[2]), "r"(a[3]), "r"(b0), "r"(b1));
}

__global__ __launch_bounds__(512, 2) void k_gemm_mma(
    const float* __restrict__ x, const float* __restrict__ W)
{
    extern __shared__ __align__(16) ushort Bs[];

    const int t    = threadIdx.x;
    const int wid  = t >> 5;
    const int lane = t & 31;
    const int g    = lane >> 2;
    const int tig  = lane & 3;

#pragma unroll 8
    for (int it = 0; it < 32; ++it) {
        int idx = t + it * 512;
        int k = idx >> 6;
        int n = idx & 63;
        float w = W[k * FOUT + n];
        __nv_bfloat16 hb = __float2bfloat16(w);
        float hf = __bfloat162float(hb);
        __nv_bfloat16 lb = __float2bfloat16(w - hf);
        Bs[B_HI_OFF + n * PAD_K + k] = __bfloat16_as_ushort(hb);
        Bs[B_LO_OFF + n * PAD_K + k] = __bfloat16_as_ushort(lb);
    }
    __syncthreads();

    const int stripe = wid & 7;
    const int nhalf  = wid >> 3;
    const int row0   = blockIdx.x * 128 + stripe * 16;

    const int row1 = row0 + g;
    const int row2 = row1 + 8;
    const bool v1 = (row1 < NN);
    const bool v2 = (row2 < NN);
    const float* xr1 = x + (size_t)row1 * FIN;
    const float* xr2 = x + (size_t)row2 * FIN;

    float acc[4][4];
#pragma unroll
    for (int i = 0; i < 4; ++i)
#pragma unroll
        for (int j = 0; j < 4; ++j) acc[i][j] = 0.0f;

#pragma unroll 4
    for (int s = 0; s < 16; ++s) {
        const int kb = s * 16 + tig * 2;

        float2 p0 = v1 ? *reinterpret_cast<const float2*>(xr1 + kb)
                       : make_float2(0.f, 0.f);
        float2 p1 = v2 ? *reinterpret_cast<const float2*>(xr2 + kb)
                       : make_float2(0.f, 0.f);
        float2 p2 = v1 ? *reinterpret_cast<const float2*>(xr1 + kb + 8)
                       : make_float2(0.f, 0.f);
        float2 p3 = v2 ? *reinterpret_cast<const float2*>(xr2 + kb + 8)
                       : make_float2(0.f, 0.f);

        uint32_t a_hi[4], a_lo[4];
        {
            __nv_bfloat16 h;
            float hf, l;
            h = __float2bfloat16(p0.x); hf = __bfloat162float(h); l = p0.x - hf;
            __nv_bfloat16 h2 = __float2bfloat16(p0.y); float hf2 = __bfloat162float(h2);
            a_hi[0] = (uint32_t)__bfloat16_as_ushort(h) | ((uint32_t)__bfloat16_as_ushort(h2) << 16);
            a_lo[0] = (uint32_t)__bfloat16_as_ushort(__float2bfloat16(l)) |
                      ((uint32_t)__bfloat16_as_ushort(__float2bfloat16(p0.y - hf2)) << 16);
            h = __float2bfloat16(p1.x); hf = __bfloat162float(h); l = p1.x - hf;
            h2 = __float2bfloat16(p1.y); hf2 = __bfloat162float(h2);
            a_hi[1] = (uint32_t)__bfloat16_as_ushort(h) | ((uint32_t)__bfloat16_as_ushort(h2) << 16);
            a_lo[1] = (uint32_t)__bfloat16_as_ushort(__float2bfloat16(l)) |
                      ((uint32_t)__bfloat16_as_ushort(__float2bfloat16(p1.y - hf2)) << 16);
            h = __float2bfloat16(p2.x); hf = __bfloat162float(h); l = p2.x - hf;
            h2 = __float2bfloat16(p2.y); hf2 = __bfloat162float(h2);
            a_hi[2] = (uint32_t)__bfloat16_as_ushort(h) | ((uint32_t)__bfloat16_as_ushort(h2) << 16);
            a_lo[2] = (uint32_t)__bfloat16_as_ushort(__float2bfloat16(l)) |
                      ((uint32_t)__bfloat16_as_ushort(__float2bfloat16(p2.y - hf2)) << 16);
            h = __float2bfloat16(p3.x); hf = __bfloat162float(h); l = p3.x - hf;
            h2 = __float2bfloat16(p3.y); hf2 = __bfloat162float(h2);
            a_hi[3] = (uint32_t)__bfloat16_as_ushort(h) | ((uint32_t)__bfloat16_as_ushort(h2) << 16);
            a_lo[3] = (uint32_t)__bfloat16_as_ushort(__float2bfloat16(l)) |
                      ((uint32_t)__bfloat16_as_ushort(__float2bfloat16(p3.y - hf2)) << 16);
        }

#pragma unroll
        for (int nt = 0; nt < 4; ++nt) {
            int n = nhalf * 32 + nt * 8 + g;
            const ushort* bh = &Bs[B_HI_OFF + n * PAD_K + kb];
            const ushort* bl = &Bs[B_LO_OFF + n * PAD_K + kb];
            uint32_t bh0 = *reinterpret_cast<const uint32_t*>(bh);
            uint32_t bh1 = *reinterpret_cast<const uint32_t*>(bh + 8);
            uint32_t bl0 = *reinterpret_cast<const uint32_t*>(bl);
            uint32_t bl1 = *reinterpret_cast<const uint32_t*>(bl + 8);
            mma_bf16(acc[nt], a_hi, bh0, bh1);
            mma_bf16(acc[nt], a_hi, bl0, bl1);
            mma_bf16(acc[nt], a_lo, bh0, bh1);
        }
    }

#pragma unroll
    for (int nt = 0; nt < 4; ++nt) {
        int c0 = nhalf * 32 + nt * 8 + tig * 2;
        if (v1)
            *reinterpret_cast<float2*>(&g_h[(size_t)row1 * FOUT + c0]) =
                make_float2(acc[nt][0], acc[nt][1]);
        if (v2)
            *reinterpret_cast<float2*>(&g_h[(size_t)row2 * FOUT + c0]) =
                make_float2(acc[nt][2], acc[nt][3]);
    }
}

// ---------------------------------------------------------------------------
// K6: CSR gather. 2 nodes per warp (16 lanes x float4 each), neighbor loop
// unrolled x4 with prefetched indices -> ~12 outstanding L2 reqs/half-warp.
__global__ __launch_bounds__(256) void k_gather(
    const float* __restrict__ bias, float* __restrict__ out)
{
    const int warp = blockIdx.x * 8 + (threadIdx.x >> 5);
    const int lane = threadIdx.x & 31;
    const int half = lane >> 4;        // 0/1: which node of the pair
    const int hl   = lane & 15;        // lane within half (float4 -> 64 floats)
    const int node = warp * 2 + half;
    if (node >= NN) return;

    const float dinv = g_deg[node];
    const int beg = g_off[node];
    const int end = g_off[node + 1];

    // self-loop term: h[node] * dinv^2
    float4 a = *reinterpret_cast<const float4*>(&g_h[(size_t)node * FOUT + hl * 4]);
    const float sl = dinv * dinv;
    a.x *= sl; a.y *= sl; a.z *= sl; a.w *= sl;

    int j = beg;
    for (; j + 4 <= end; j += 4) {
        int s0 = g_nbr[j];
        int s1 = g_nbr[j + 1];
        int s2 = g_nbr[j + 2];
        int s3 = g_nbr[j + 3];
        float n0 = dinv * g_deg[s0];
        float n1 = dinv * g_deg[s1];
        float n2 = dinv * g_deg[s2];
        float n3 = dinv * g_deg[s3];
        float4 v0 = *reinterpret_cast<const float4*>(&g_h[(size_t)s0 * FOUT + hl * 4]);
        float4 v1 = *reinterpret_cast<const float4*>(&g_h[(size_t)s1 * FOUT + hl * 4]);
        float4 v2 = *reinterpret_cast<const float4*>(&g_h[(size_t)s2 * FOUT + hl * 4]);
        float4 v3 = *reinterpret_cast<const float4*>(&g_h[(size_t)s3 * FOUT + hl * 4]);
        a.x = fmaf(v0.x, n0, a.x); a.y = fmaf(v0.y, n0, a.y);
        a.z = fmaf(v0.z, n0, a.z); a.w = fmaf(v0.w, n0, a.w);
        a.x = fmaf(v1.x, n1, a.x); a.y = fmaf(v1.y, n1, a.y);
        a.z = fmaf(v1.z, n1, a.z); a.w = fmaf(v1.w, n1, a.w);
        a.x = fmaf(v2.x, n2, a.x); a.y = fmaf(v2.y, n2, a.y);
        a.z = fmaf(v2.z, n2, a.z); a.w = fmaf(v2.w, n2, a.w);
        a.x = fmaf(v3.x, n3, a.x); a.y = fmaf(v3.y, n3, a.y);
        a.z = fmaf(v3.z, n3, a.z); a.w = fmaf(v3.w, n3, a.w);
    }
    for (; j < end; ++j) {
        int s0 = g_nbr[j];
        float n0 = dinv * g_deg[s0];
        float4 v0 = *reinterpret_cast<const float4*>(&g_h[(size_t)s0 * FOUT + hl * 4]);
        a.x = fmaf(v0.x, n0, a.x); a.y = fmaf(v0.y, n0, a.y);
        a.z = fmaf(v0.z, n0, a.z); a.w = fmaf(v0.w, n0, a.w);
    }

    float4 bb = *reinterpret_cast<const float4*>(bias + hl * 4);
    a.x = fmaxf(a.x + bb.x, 0.f);
    a.y = fmaxf(a.y + bb.y, 0.f);
    a.z = fmaxf(a.z + bb.z, 0.f);
    a.w = fmaxf(a.w + bb.w, 0.f);
    *reinterpret_cast<float4*>(&out[(size_t)node * FOUT + hl * 4]) = a;
}

// ---------------------------------------------------------------------------
extern "C" void kernel_launch(void* const* d_in, const int* in_sizes, int n_in,
                              void* d_out, int out_size)
{
    const float* x   = (const float*)d_in[0];   // [N, 256]
    const int*   adj = (const int*)d_in[1];     // [2, E]
    const float* W   = (const float*)d_in[2];   // [256, 64]
    const float* b   = (const float*)d_in[3];   // [64]
    float*       out = (float*)d_out;           // [N, 64]

    const int* src = adj;
    const int* dst = adj + EE;

    static bool attr_set = false;
    if (!attr_set) {
        cudaFuncSetAttribute(k_gemm_mma,
                             cudaFuncAttributeMaxDynamicSharedMemorySize, GEMM_SMEM);
        attr_set = true;
    }

    // CSR build
    k_zero<<<(NN + 255) / 256, 256>>>();
    k_count<<<(EE / 4 + 255) / 256, 256>>>(dst);
    k_scan_a<<<NBLK, 1024>>>();
    k_scan_b<<<1, 64>>>();
    k_scan_c<<<NBLK, 1024>>>();
    k_fill<<<(EE / 4 + 255) / 256, 256>>>(src, dst);

    // GEMM (mma.sync bf16 split)
    k_gemm_mma<<<(NN + 127) / 128, 512, GEMM_SMEM>>>(x, W);

    // fused gather + self loop + bias + relu
    k_gather<<<(NN / 2 + 7) / 8, 256>>>(b, out);
}